// round 1
// baseline (speedup 1.0000x reference)
#include <cuda_runtime.h>
#include <math.h>

#define Bb   32
#define Kk   64
#define Dd   256
#define LSs  128
#define NLl  2
#define Mm   (Bb*Kk)          // 2048 rows

// ---------------- scratch (no allocs allowed) ----------------
__device__ float g_x  [Mm*Dd];
__device__ float g_k  [Mm*Dd];
__device__ float g_q  [Mm*Dd];
__device__ float g_a  [Mm*Dd];
__device__ float g_bbf[Mm*Dd];
__device__ float g_gg [Mm*Dd];
__device__ float g_hp [Mm*Dd];
__device__ float g_h  [Mm*Dd];
__device__ float g_t  [Mm*Dd];
__device__ float g_ws [Dd*Dd];
__device__ float g_s  [Bb*Dd];

__device__ __forceinline__ float gelu_exact(float x) {
    return 0.5f * x * (1.0f + erff(x * 0.7071067811865476f));
}

// ---------------- misc small kernels ----------------
__global__ void copy_kernel(const float* __restrict__ src, float* __restrict__ dst, int n) {
    int i = blockIdx.x * blockDim.x + threadIdx.x;
    if (i < n) dst[i] = src[i];
}

// wsum[d,c] = W1a[d,c] + W1b[d,c]   (rv_w1 row d = [W1a(256) | W1b(256)])
__global__ void wsum_kernel(const float* __restrict__ w1, float* __restrict__ ws) {
    int i = blockIdx.x * blockDim.x + threadIdx.x;   // i in [0, D*D)
    int d = i >> 8, c = i & 255;
    ws[i] = w1[d * (2 * Dd) + c] + w1[d * (2 * Dd) + Dd + c];
}

// ---------------- SGEMM: C[M,N] = A[M,Kd] * Bw[N,Kd]^T (+bias)(+gelu)(+resid) ----------------
// Tiles: 64x64x16, 256 threads, 4x4 per thread. M,N % 64 == 0, Kd % 16 == 0.
__global__ void __launch_bounds__(256)
sgemm_kernel(const float* __restrict__ A, int lda,
             const float* __restrict__ Bw, int ldb,
             const float* __restrict__ bias,
             const float* __restrict__ resid,
             float* __restrict__ C,
             int N, int Kd, int do_gelu)
{
    __shared__ float As[16][68];
    __shared__ float Bs[16][68];

    const int bm = blockIdx.y * 64;
    const int bn = blockIdx.x * 64;
    const int tid = threadIdx.x;
    const int row = tid >> 2;        // 0..63 (load row)
    const int seg = tid & 3;         // 0..3  (load K segment of 4)
    const int ty  = tid >> 4;        // 0..15 (m tile)
    const int tx  = tid & 15;        // 0..15 (n tile)

    float acc[4][4] = {};

    for (int k0 = 0; k0 < Kd; k0 += 16) {
        float4 va = *reinterpret_cast<const float4*>(&A [(bm + row) * lda + k0 + seg * 4]);
        float4 vb = *reinterpret_cast<const float4*>(&Bw[(bn + row) * ldb + k0 + seg * 4]);
        As[seg * 4 + 0][row] = va.x; As[seg * 4 + 1][row] = va.y;
        As[seg * 4 + 2][row] = va.z; As[seg * 4 + 3][row] = va.w;
        Bs[seg * 4 + 0][row] = vb.x; Bs[seg * 4 + 1][row] = vb.y;
        Bs[seg * 4 + 2][row] = vb.z; Bs[seg * 4 + 3][row] = vb.w;
        __syncthreads();

        #pragma unroll
        for (int kk = 0; kk < 16; kk++) {
            float4 a4 = *reinterpret_cast<const float4*>(&As[kk][ty * 4]);
            float4 b4 = *reinterpret_cast<const float4*>(&Bs[kk][tx * 4]);
            float av[4] = {a4.x, a4.y, a4.z, a4.w};
            float bv[4] = {b4.x, b4.y, b4.z, b4.w};
            #pragma unroll
            for (int i = 0; i < 4; i++)
                #pragma unroll
                for (int j = 0; j < 4; j++)
                    acc[i][j] = fmaf(av[i], bv[j], acc[i][j]);
        }
        __syncthreads();
    }

    #pragma unroll
    for (int i = 0; i < 4; i++) {
        int r = bm + ty * 4 + i;
        #pragma unroll
        for (int j = 0; j < 4; j++) {
            int c = bn + tx * 4 + j;
            float v = acc[i][j];
            if (bias)  v += bias[c];
            if (do_gelu) v = gelu_exact(v);
            if (resid) v += resid[r * N + c];
            C[r * N + c] = v;
        }
    }
}

// ---------------- attention + gelu-weighted aggregation ----------------
// block (i, b), 256 threads. g[b,i,d] = sum_j softmax_j(q_i . k_j * scale) * gelu(a_i[d]-bb_j[d])
__global__ void __launch_bounds__(256)
attn_kernel(const float* __restrict__ q, const float* __restrict__ k,
            const float* __restrict__ a, const float* __restrict__ bb,
            float* __restrict__ g)
{
    const int i = blockIdx.x, b = blockIdx.y;
    const int tid = threadIdx.x;
    const int lane = tid & 31, warp = tid >> 5;

    __shared__ float sq[Dd];
    __shared__ float sl[Kk];
    __shared__ float sp[Kk];

    const float* qi  = q  + (b * Kk + i) * Dd;
    const float* kb  = k  + b * Kk * Dd;
    const float* bbb = bb + b * Kk * Dd;
    const float* ai  = a  + (b * Kk + i) * Dd;

    sq[tid] = qi[tid];
    __syncthreads();

    // logits: warp w -> j = w, w+8, ...
    for (int j = warp; j < Kk; j += 8) {
        const float* kj = kb + j * Dd;
        float s = 0.f;
        #pragma unroll
        for (int d = lane; d < Dd; d += 32) s = fmaf(sq[d], kj[d], s);
        #pragma unroll
        for (int o = 16; o; o >>= 1) s += __shfl_xor_sync(0xffffffffu, s, o);
        if (lane == 0) sl[j] = s * 0.0625f;   // D^-0.5 = 1/16
    }
    __syncthreads();

    // softmax over 64 (first warp, 2 per lane)
    if (tid < 32) {
        float v0 = sl[tid], v1 = sl[tid + 32];
        float m = fmaxf(v0, v1);
        #pragma unroll
        for (int o = 16; o; o >>= 1) m = fmaxf(m, __shfl_xor_sync(0xffffffffu, m, o));
        float e0 = __expf(v0 - m), e1 = __expf(v1 - m);
        float s = e0 + e1;
        #pragma unroll
        for (int o = 16; o; o >>= 1) s += __shfl_xor_sync(0xffffffffu, s, o);
        float inv = 1.f / s;
        sp[tid] = e0 * inv; sp[tid + 32] = e1 * inv;
    }
    __syncthreads();

    // aggregation: thread owns dimension d = tid
    const float ad = ai[tid];
    float accv = 0.f;
    #pragma unroll 4
    for (int j = 0; j < Kk; j++)
        accv = fmaf(sp[j], gelu_exact(ad - bbb[j * Dd + tid]), accv);
    g[(b * Kk + i) * Dd + tid] = accv;
}

// ---------------- layernorm over D=256, block per row ----------------
__device__ __forceinline__ float blocksum256(float v, float* red) {
    int lane = threadIdx.x & 31, w = threadIdx.x >> 5;
    #pragma unroll
    for (int o = 16; o; o >>= 1) v += __shfl_xor_sync(0xffffffffu, v, o);
    __syncthreads();
    if (lane == 0) red[w] = v;
    __syncthreads();
    float t = red[0];
    #pragma unroll
    for (int i = 1; i < 8; i++) t += red[i];
    return t;
}

__global__ void __launch_bounds__(256)
ln_kernel(const float* __restrict__ in, const float* __restrict__ gam,
          const float* __restrict__ bet, float* __restrict__ out)
{
    __shared__ float red[8];
    int r = blockIdx.x, tid = threadIdx.x;
    float v = in[r * Dd + tid];
    float mean = blocksum256(v, red) * (1.f / Dd);
    float dv = v - mean;
    float var = blocksum256(dv * dv, red) * (1.f / Dd);
    out[r * Dd + tid] = dv * rsqrtf(var + 1e-5f) * gam[tid] + bet[tid];
}

// ---------------- pool: s[b,d] = sum_i x[b,i,d] ----------------
__global__ void __launch_bounds__(256)
pool_kernel(const float* __restrict__ x, float* __restrict__ s)
{
    int b = blockIdx.x, d = threadIdx.x;
    float acc = 0.f;
    #pragma unroll 8
    for (int i = 0; i < Kk; i++) acc += x[(b * Kk + i) * Dd + d];
    s[b * Dd + d] = acc;
}

// ---------------- heads: gelu(s@Pw^T+pb) -> mu / softplus ----------------
__global__ void __launch_bounds__(LSs)
head_kernel(const float* __restrict__ s,
            const float* __restrict__ pw, const float* __restrict__ pb,
            const float* __restrict__ muw, const float* __restrict__ mub,
            const float* __restrict__ spw, const float* __restrict__ spb,
            float* __restrict__ out)
{
    int b = blockIdx.x, n = threadIdx.x;   // n < 128
    __shared__ float ss[Dd];
    __shared__ float sh[LSs];
    ss[n]       = s[b * Dd + n];
    ss[n + 128] = s[b * Dd + n + 128];
    __syncthreads();

    float acc = pb[n];
    #pragma unroll 8
    for (int d = 0; d < Dd; d++) acc = fmaf(ss[d], pw[n * Dd + d], acc);
    sh[n] = gelu_exact(acc);
    __syncthreads();

    float mu = mub[n], sc = spb[n];
    #pragma unroll 8
    for (int d = 0; d < LSs; d++) {
        mu = fmaf(sh[d], muw[n * LSs + d], mu);
        sc = fmaf(sh[d], spw[n * LSs + d], sc);
    }
    // stable softplus: max(x,0) + log1p(exp(-|x|))
    float spv = fmaxf(sc, 0.f) + log1pf(expf(-fabsf(sc)));
    out[b * LSs + n] = mu;
    out[Bb * LSs + b * LSs + n] = spv;
}

// ---------------- launch ----------------
extern "C" void kernel_launch(void* const* d_in, const int* in_sizes, int n_in,
                              void* d_out, int out_size)
{
    (void)in_sizes; (void)n_in; (void)out_size;
    const float* X    = (const float*)d_in[0];
    const float* k_w  = (const float*)d_in[1];
    const float* q_w  = (const float*)d_in[2];
    const float* rw1  = (const float*)d_in[3];
    const float* rb1  = (const float*)d_in[4];
    const float* rw2  = (const float*)d_in[5];
    const float* rb2  = (const float*)d_in[6];
    const float* lng  = (const float*)d_in[7];
    const float* lnb  = (const float*)d_in[8];
    const float* mw1  = (const float*)d_in[9];
    const float* mb1  = (const float*)d_in[10];
    const float* mw2  = (const float*)d_in[11];
    const float* mb2  = (const float*)d_in[12];
    const float* pw   = (const float*)d_in[13];
    const float* pb   = (const float*)d_in[14];
    const float* muw  = (const float*)d_in[15];
    const float* mub  = (const float*)d_in[16];
    const float* spw  = (const float*)d_in[17];
    const float* spb  = (const float*)d_in[18];
    float* out = (float*)d_out;

    static float *px=nullptr,*pk=nullptr,*pq=nullptr,*pa=nullptr,*pbb=nullptr,
                 *pgg=nullptr,*php=nullptr,*ph=nullptr,*pt=nullptr,*pws=nullptr,*ps=nullptr;
    if (!px) {
        cudaGetSymbolAddress((void**)&px,  g_x);
        cudaGetSymbolAddress((void**)&pk,  g_k);
        cudaGetSymbolAddress((void**)&pq,  g_q);
        cudaGetSymbolAddress((void**)&pa,  g_a);
        cudaGetSymbolAddress((void**)&pbb, g_bbf);
        cudaGetSymbolAddress((void**)&pgg, g_gg);
        cudaGetSymbolAddress((void**)&php, g_hp);
        cudaGetSymbolAddress((void**)&ph,  g_h);
        cudaGetSymbolAddress((void**)&pt,  g_t);
        cudaGetSymbolAddress((void**)&pws, g_ws);
        cudaGetSymbolAddress((void**)&ps,  g_s);
    }

    copy_kernel<<<(Mm * Dd) / 256, 256>>>(X, px, Mm * Dd);

    dim3 gg(Dd / 64, Mm / 64);   // (4, 32)

    for (int l = 0; l < NLl; l++) {
        const float* kw_l  = k_w + l * Dd * Dd;
        const float* qw_l  = q_w + l * Dd * Dd;
        const float* rw1_l = rw1 + l * Dd * 2 * Dd;
        const float* rb1_l = rb1 + l * Dd;
        const float* rw2_l = rw2 + l * Dd * Dd;
        const float* rb2_l = rb2 + l * Dd;
        const float* lg_l  = lng + l * Dd;
        const float* lb_l  = lnb + l * Dd;
        const float* mw1_l = mw1 + l * Dd * Dd;
        const float* mb1_l = mb1 + l * Dd;
        const float* mw2_l = mw2 + l * Dd * Dd;
        const float* mb2_l = mb2 + l * Dd;

        wsum_kernel<<<(Dd * Dd) / 256, 256>>>(rw1_l, pws);

        sgemm_kernel<<<gg, 256>>>(px, Dd, kw_l,       Dd,     nullptr, nullptr, pk,  Dd, Dd, 0);
        sgemm_kernel<<<gg, 256>>>(px, Dd, qw_l,       Dd,     nullptr, nullptr, pq,  Dd, Dd, 0);
        sgemm_kernel<<<gg, 256>>>(px, Dd, pws,        Dd,     rb1_l,   nullptr, pa,  Dd, Dd, 0);
        sgemm_kernel<<<gg, 256>>>(px, Dd, rw1_l + Dd, 2 * Dd, nullptr, nullptr, pbb, Dd, Dd, 0);

        attn_kernel<<<dim3(Kk, Bb), 256>>>(pq, pk, pa, pbb, pgg);

        sgemm_kernel<<<gg, 256>>>(pgg, Dd, rw2_l, Dd, rb2_l, px, php, Dd, Dd, 0);
        ln_kernel<<<Mm, 256>>>(php, lg_l, lb_l, ph);
        sgemm_kernel<<<gg, 256>>>(ph, Dd, mw1_l, Dd, mb1_l, nullptr, pt, Dd, Dd, 1);
        sgemm_kernel<<<gg, 256>>>(pt, Dd, mw2_l, Dd, mb2_l, px,      px, Dd, Dd, 0);
    }

    pool_kernel<<<Bb, 256>>>(px, ps);
    head_kernel<<<Bb, LSs>>>(ps, pw, pb, muw, mub, spw, spb, out);
}

// round 4
// speedup vs baseline: 1.3724x; 1.3724x over previous
#include <cuda_runtime.h>
#include <cuda_bf16.h>
#include <math.h>
#include <cstdint>

#define Bb   32
#define Kk   64
#define Dd   256
#define LSs  128
#define NLl  2
#define Mm   (Bb*Kk)          // 2048 rows
#define QS   1024             // qkab row stride
#define GK   256              // GEMM K

// ---------------- scratch (no allocs allowed) ----------------
__device__ float g_x   [Mm*Dd];
__device__ float g_qkab[Mm*QS];
__device__ float g_gg  [Mm*Dd];
__device__ float g_hp  [Mm*Dd];
__device__ float g_h   [Mm*Dd];
__device__ float g_t   [Mm*Dd];
__device__ float g_wc  [4*Dd*Dd];
__device__ float g_bc  [4*Dd];
__device__ float g_s   [Bb*Dd];

__device__ __forceinline__ float gelu_exact(float x) {
    return 0.5f * x * (1.0f + erff(x * 0.7071067811865476f));
}

__device__ __forceinline__ uint32_t smem_u32(const void* p) {
    uint32_t a;
    asm("{ .reg .u64 t; cvta.to.shared.u64 t, %1; cvt.u32.u64 %0, t; }" : "=r"(a) : "l"(p));
    return a;
}

// ---------------- warp MMA primitives (baseline ISA, valid on sm_103) ----------------
__device__ __forceinline__ void ldsm_x4(uint32_t* r, uint32_t addr) {
    asm volatile("ldmatrix.sync.aligned.m8n8.x4.shared.b16 {%0,%1,%2,%3}, [%4];"
        : "=r"(r[0]), "=r"(r[1]), "=r"(r[2]), "=r"(r[3]) : "r"(addr));
}
__device__ __forceinline__ void ldsm_x2(uint32_t* r, uint32_t addr) {
    asm volatile("ldmatrix.sync.aligned.m8n8.x2.shared.b16 {%0,%1}, [%2];"
        : "=r"(r[0]), "=r"(r[1]) : "r"(addr));
}
__device__ __forceinline__ void mma_bf16(float* c, const uint32_t* a, const uint32_t* b) {
    asm volatile("mma.sync.aligned.m16n8k16.row.col.f32.bf16.bf16.f32 "
        "{%0,%1,%2,%3}, {%4,%5,%6,%7}, {%8,%9}, {%0,%1,%2,%3};"
        : "+f"(c[0]), "+f"(c[1]), "+f"(c[2]), "+f"(c[3])
        : "r"(a[0]), "r"(a[1]), "r"(a[2]), "r"(a[3]), "r"(b[0]), "r"(b[1]));
}

// ---------------- smem layout for tc_gemm ----------------
// padded row-major bf16 tiles; row stride 264 bf16 = 528 B (conflict-free ldmatrix)
#define LDSB  528
#define SM_AH 0
#define SM_AL (SM_AH + 128*LDSB)
#define SM_BH (SM_AL + 128*LDSB)
#define SM_BL (SM_BH + 64*LDSB)
#define SM_TOT (SM_BL + 64*LDSB)     // 202752 B

// convert fp32 tile [ROWS,256] -> bf16 hi/lo tiles in smem
template<int ROWS>
__device__ __forceinline__ void stage_tile(const float* __restrict__ G,
                                           char* sm_hi, char* sm_lo, int tid) {
    const int ngroups = ROWS * (GK / 8);
    for (int g = tid; g < ngroups; g += 256) {
        int row = g >> 5;
        int k0  = (g & 31) * 8;
        const float* src = G + (size_t)row * GK + k0;
        float4 v0 = *(const float4*)(src);
        float4 v1 = *(const float4*)(src + 4);
        float f[8] = {v0.x, v0.y, v0.z, v0.w, v1.x, v1.y, v1.z, v1.w};
        uint32_t hi[4], lo[4];
        #pragma unroll
        for (int p = 0; p < 4; p++) {
            float a = f[2 * p], b = f[2 * p + 1];
            uint32_t h;
            asm("cvt.rn.bf16x2.f32 %0, %1, %2;" : "=r"(h) : "f"(b), "f"(a));
            float ha = __uint_as_float(h << 16);
            float hb = __uint_as_float(h & 0xffff0000u);
            float la = a - ha, lb = b - hb;
            uint32_t l;
            asm("cvt.rn.bf16x2.f32 %0, %1, %2;" : "=r"(l) : "f"(lb), "f"(la));
            hi[p] = h; lo[p] = l;
        }
        uint32_t off = (uint32_t)(row * LDSB + k0 * 2);
        *(uint4*)(sm_hi + off) = make_uint4(hi[0], hi[1], hi[2], hi[3]);
        *(uint4*)(sm_lo + off) = make_uint4(lo[0], lo[1], lo[2], lo[3]);
    }
}

// ---------------- bf16x3 GEMM: C[.,N] = A[M,256] @ Bw[N,256]^T (+bias)(+gelu)(+resid) ----
// CTA: 128x64 tile, 8 warps (4M x 2N), warp tile 32x32 = 2x4 m16n8k16.
__global__ void __launch_bounds__(256)
tc_gemm(const float* __restrict__ A, const float* __restrict__ Bw,
        const float* __restrict__ bias, const float* __restrict__ resid,
        float* __restrict__ C, int ldc, int do_gelu)
{
    extern __shared__ char sm[];
    uint32_t smb = smem_u32(sm);
    const int tid = threadIdx.x, lane = tid & 31, wid = tid >> 5;
    const int warp_m = wid & 3, warp_n = wid >> 2;
    const int bm = blockIdx.y * 128, bn = blockIdx.x * 64;

    stage_tile<128>(A  + (size_t)bm * GK, sm + SM_AH, sm + SM_AL, tid);
    stage_tile<64>( Bw + (size_t)bn * GK, sm + SM_BH, sm + SM_BL, tid);
    __syncthreads();

    float acc[2][4][4];
    #pragma unroll
    for (int i = 0; i < 2; i++)
        #pragma unroll
        for (int j = 0; j < 4; j++)
            #pragma unroll
            for (int e = 0; e < 4; e++) acc[i][j][e] = 0.f;

    // per-lane ldmatrix base addresses
    uint32_t a_base[2], b_base[4];
    #pragma unroll
    for (int tm = 0; tm < 2; tm++)
        a_base[tm] = smb + SM_AH
                   + (uint32_t)((warp_m * 32 + tm * 16 + (lane & 15)) * LDSB)
                   + (uint32_t)((lane >> 4) * 16);
    #pragma unroll
    for (int tn = 0; tn < 4; tn++)
        b_base[tn] = smb + SM_BH
                   + (uint32_t)((warp_n * 32 + tn * 8 + (lane & 7)) * LDSB)
                   + (uint32_t)(((lane >> 3) & 1) * 16);

    const uint32_t DA = SM_AL - SM_AH;
    const uint32_t DB = SM_BL - SM_BH;

    #pragma unroll
    for (int ks = 0; ks < 16; ks++) {
        const uint32_t kb = ks * 32;   // 16 bf16 = 32 bytes
        uint32_t ah[2][4], al[2][4], bh[4][2], bl[4][2];
        #pragma unroll
        for (int tm = 0; tm < 2; tm++) {
            ldsm_x4(ah[tm], a_base[tm] + kb);
            ldsm_x4(al[tm], a_base[tm] + kb + DA);
        }
        #pragma unroll
        for (int tn = 0; tn < 4; tn++) {
            ldsm_x2(bh[tn], b_base[tn] + kb);
            ldsm_x2(bl[tn], b_base[tn] + kb + DB);
        }
        #pragma unroll
        for (int tm = 0; tm < 2; tm++)
            #pragma unroll
            for (int tn = 0; tn < 4; tn++) {
                mma_bf16(acc[tm][tn], ah[tm], bh[tn]);
                mma_bf16(acc[tm][tn], ah[tm], bl[tn]);
                mma_bf16(acc[tm][tn], al[tm], bh[tn]);
            }
    }

    // epilogue: c0,c1 -> (row, col..col+1); c2,c3 -> (row+8, col..col+1)
    #pragma unroll
    for (int tm = 0; tm < 2; tm++) {
        int r0 = bm + warp_m * 32 + tm * 16 + (lane >> 2);
        #pragma unroll
        for (int tn = 0; tn < 4; tn++) {
            int c = bn + warp_n * 32 + tn * 8 + (lane & 3) * 2;
            #pragma unroll
            for (int h = 0; h < 2; h++) {
                int r = r0 + h * 8;
                float x0 = acc[tm][tn][h * 2 + 0];
                float x1 = acc[tm][tn][h * 2 + 1];
                if (bias)  { x0 += bias[c]; x1 += bias[c + 1]; }
                if (do_gelu) { x0 = gelu_exact(x0); x1 = gelu_exact(x1); }
                if (resid) {
                    float2 rr = *(const float2*)(resid + (size_t)r * ldc + c);
                    x0 += rr.x; x1 += rr.y;
                }
                *(float2*)(C + (size_t)r * ldc + c) = make_float2(x0, x1);
            }
        }
    }
}

// ---------------- misc small kernels ----------------
__global__ void copy_kernel(const float* __restrict__ src, float* __restrict__ dst, int n) {
    int i = blockIdx.x * blockDim.x + threadIdx.x;
    if (i < n) dst[i] = src[i];
}

// pack combined weights: rows [0:256)=k_w, [256:512)=q_w, [512:768)=W1a+W1b, [768:1024)=W1b
__global__ void pack_kernel(const float* __restrict__ kw, const float* __restrict__ qw,
                            const float* __restrict__ w1, const float* __restrict__ rb1,
                            float* __restrict__ wc, float* __restrict__ bc) {
    int i = blockIdx.x * blockDim.x + threadIdx.x;   // [0, 1024*256)
    int r = i >> 8, c = i & 255;
    float v;
    if (r < 256)      v = kw[r * Dd + c];
    else if (r < 512) v = qw[(r - 256) * Dd + c];
    else if (r < 768) { int d = r - 512; v = w1[d * 2 * Dd + c] + w1[d * 2 * Dd + Dd + c]; }
    else              { int d = r - 768; v = w1[d * 2 * Dd + Dd + c]; }
    wc[i] = v;
    if (i < 4 * Dd) bc[i] = (i >= 512 && i < 768) ? rb1[i - 512] : 0.f;
}

// ---------------- attention + gelu-weighted aggregation ----------------
// qkab row layout: [k(256) | q(256) | a(256) | bb(256)]
__global__ void __launch_bounds__(256)
attn_kernel(const float* __restrict__ qkab, float* __restrict__ g)
{
    const int i = blockIdx.x, b = blockIdx.y;
    const int tid = threadIdx.x;
    const int lane = tid & 31, warp = tid >> 5;

    __shared__ float sq[Dd];
    __shared__ float sl[Kk];
    __shared__ float sp[Kk];

    const float* rowi = qkab + (size_t)(b * Kk + i) * QS;
    const float* base = qkab + (size_t)b * Kk * QS;

    sq[tid] = rowi[256 + tid];     // q
    __syncthreads();

    for (int j = warp; j < Kk; j += 8) {
        const float* kj = base + (size_t)j * QS;   // k at offset 0
        float s = 0.f;
        #pragma unroll
        for (int d = lane; d < Dd; d += 32) s = fmaf(sq[d], kj[d], s);
        #pragma unroll
        for (int o = 16; o; o >>= 1) s += __shfl_xor_sync(0xffffffffu, s, o);
        if (lane == 0) sl[j] = s * 0.0625f;        // D^-0.5
    }
    __syncthreads();

    if (tid < 32) {
        float v0 = sl[tid], v1 = sl[tid + 32];
        float m = fmaxf(v0, v1);
        #pragma unroll
        for (int o = 16; o; o >>= 1) m = fmaxf(m, __shfl_xor_sync(0xffffffffu, m, o));
        float e0 = __expf(v0 - m), e1 = __expf(v1 - m);
        float s = e0 + e1;
        #pragma unroll
        for (int o = 16; o; o >>= 1) s += __shfl_xor_sync(0xffffffffu, s, o);
        float inv = 1.f / s;
        sp[tid] = e0 * inv; sp[tid + 32] = e1 * inv;
    }
    __syncthreads();

    const float ad = rowi[512 + tid];              // a
    float accv = 0.f;
    #pragma unroll 4
    for (int j = 0; j < Kk; j++)
        accv = fmaf(sp[j], gelu_exact(ad - base[(size_t)j * QS + 768 + tid]), accv);
    g[(size_t)(b * Kk + i) * Dd + tid] = accv;
}

// ---------------- layernorm over D=256 ----------------
__device__ __forceinline__ float blocksum256(float v, float* red) {
    int lane = threadIdx.x & 31, w = threadIdx.x >> 5;
    #pragma unroll
    for (int o = 16; o; o >>= 1) v += __shfl_xor_sync(0xffffffffu, v, o);
    __syncthreads();
    if (lane == 0) red[w] = v;
    __syncthreads();
    float t = red[0];
    #pragma unroll
    for (int i = 1; i < 8; i++) t += red[i];
    return t;
}

__global__ void __launch_bounds__(256)
ln_kernel(const float* __restrict__ in, const float* __restrict__ gam,
          const float* __restrict__ bet, float* __restrict__ out)
{
    __shared__ float red[8];
    int r = blockIdx.x, tid = threadIdx.x;
    float v = in[r * Dd + tid];
    float mean = blocksum256(v, red) * (1.f / Dd);
    float dv = v - mean;
    float var = blocksum256(dv * dv, red) * (1.f / Dd);
    out[r * Dd + tid] = dv * rsqrtf(var + 1e-5f) * gam[tid] + bet[tid];
}

// ---------------- pool + heads ----------------
__global__ void __launch_bounds__(256)
pool_kernel(const float* __restrict__ x, float* __restrict__ s)
{
    int b = blockIdx.x, d = threadIdx.x;
    float acc = 0.f;
    #pragma unroll 8
    for (int i = 0; i < Kk; i++) acc += x[(b * Kk + i) * Dd + d];
    s[b * Dd + d] = acc;
}

__global__ void __launch_bounds__(LSs)
head_kernel(const float* __restrict__ s,
            const float* __restrict__ pw, const float* __restrict__ pb,
            const float* __restrict__ muw, const float* __restrict__ mub,
            const float* __restrict__ spw, const float* __restrict__ spb,
            float* __restrict__ out)
{
    int b = blockIdx.x, n = threadIdx.x;
    __shared__ float ss[Dd];
    __shared__ float sh[LSs];
    ss[n]       = s[b * Dd + n];
    ss[n + 128] = s[b * Dd + n + 128];
    __syncthreads();

    float acc = pb[n];
    #pragma unroll 8
    for (int d = 0; d < Dd; d++) acc = fmaf(ss[d], pw[n * Dd + d], acc);
    sh[n] = gelu_exact(acc);
    __syncthreads();

    float mu = mub[n], sc = spb[n];
    #pragma unroll 8
    for (int d = 0; d < LSs; d++) {
        mu = fmaf(sh[d], muw[n * LSs + d], mu);
        sc = fmaf(sh[d], spw[n * LSs + d], sc);
    }
    float spv = fmaxf(sc, 0.f) + log1pf(expf(-fabsf(sc)));
    out[b * LSs + n] = mu;
    out[Bb * LSs + b * LSs + n] = spv;
}

// ---------------- launch ----------------
extern "C" void kernel_launch(void* const* d_in, const int* in_sizes, int n_in,
                              void* d_out, int out_size)
{
    (void)in_sizes; (void)n_in; (void)out_size;
    const float* X    = (const float*)d_in[0];
    const float* k_w  = (const float*)d_in[1];
    const float* q_w  = (const float*)d_in[2];
    const float* rw1  = (const float*)d_in[3];
    const float* rb1  = (const float*)d_in[4];
    const float* rw2  = (const float*)d_in[5];
    const float* rb2  = (const float*)d_in[6];
    const float* lng  = (const float*)d_in[7];
    const float* lnb  = (const float*)d_in[8];
    const float* mw1  = (const float*)d_in[9];
    const float* mb1  = (const float*)d_in[10];
    const float* mw2  = (const float*)d_in[11];
    const float* mb2  = (const float*)d_in[12];
    const float* pw   = (const float*)d_in[13];
    const float* pb   = (const float*)d_in[14];
    const float* muw  = (const float*)d_in[15];
    const float* mub  = (const float*)d_in[16];
    const float* spw  = (const float*)d_in[17];
    const float* spb  = (const float*)d_in[18];
    float* out = (float*)d_out;

    static float *px=nullptr,*pqkab=nullptr,*pgg=nullptr,*php=nullptr,*ph=nullptr,
                 *pt=nullptr,*pwc=nullptr,*pbc=nullptr,*ps=nullptr;
    if (!px) {
        cudaGetSymbolAddress((void**)&px,    g_x);
        cudaGetSymbolAddress((void**)&pqkab, g_qkab);
        cudaGetSymbolAddress((void**)&pgg,   g_gg);
        cudaGetSymbolAddress((void**)&php,   g_hp);
        cudaGetSymbolAddress((void**)&ph,    g_h);
        cudaGetSymbolAddress((void**)&pt,    g_t);
        cudaGetSymbolAddress((void**)&pwc,   g_wc);
        cudaGetSymbolAddress((void**)&pbc,   g_bc);
        cudaGetSymbolAddress((void**)&ps,    g_s);
        cudaFuncSetAttribute(tc_gemm, cudaFuncAttributeMaxDynamicSharedMemorySize, SM_TOT);
    }

    copy_kernel<<<(Mm * Dd) / 256, 256>>>(X, px, Mm * Dd);

    for (int l = 0; l < NLl; l++) {
        const float* rw1_l = rw1 + l * Dd * 2 * Dd;
        const float* rb1_l = rb1 + l * Dd;
        const float* rw2_l = rw2 + l * Dd * Dd;
        const float* rb2_l = rb2 + l * Dd;
        const float* lg_l  = lng + l * Dd;
        const float* lb_l  = lnb + l * Dd;
        const float* mw1_l = mw1 + l * Dd * Dd;
        const float* mb1_l = mb1 + l * Dd;
        const float* mw2_l = mw2 + l * Dd * Dd;
        const float* mb2_l = mb2 + l * Dd;

        pack_kernel<<<(4 * Dd * Dd) / 256, 256>>>(k_w + l * Dd * Dd, q_w + l * Dd * Dd,
                                                  rw1_l, rb1_l, pwc, pbc);

        // fused k|q|a|bb projection: [2048,256] @ [1024,256]^T
        tc_gemm<<<dim3(16, 16), 256, SM_TOT>>>(px, pwc, pbc, nullptr, pqkab, QS, 0);

        attn_kernel<<<dim3(Kk, Bb), 256>>>(pqkab, pgg);

        tc_gemm<<<dim3(4, 16), 256, SM_TOT>>>(pgg, rw2_l, rb2_l, px, php, Dd, 0);
        ln_kernel<<<Mm, 256>>>(php, lg_l, lb_l, ph);
        tc_gemm<<<dim3(4, 16), 256, SM_TOT>>>(ph, mw1_l, mb1_l, nullptr, pt, Dd, 1);
        tc_gemm<<<dim3(4, 16), 256, SM_TOT>>>(pt, mw2_l, mb2_l, px, px, Dd, 0);
    }

    pool_kernel<<<Bb, 256>>>(px, ps);
    head_kernel<<<Bb, LSs>>>(ps, pw, pb, muw, mub, spw, spb, out);
}